// round 1
// baseline (speedup 1.0000x reference)
#include <cuda_runtime.h>
#include <cstddef>

#define N_ROWS 4096
#define CH     256
#define NC     1000

// ---- scratch (static device globals; no runtime allocation) ----
__device__ float g_invn[N_ROWS];
__device__ int   g_cls[N_ROWS];
__device__ float g_G[CH * CH];
__device__ float g_sums[NC * CH];
__device__ float g_counts[NC];

// ---------------------------------------------------------------
// K0: zero the accumulators (must be re-zeroed every call: graph-replayable)
// ---------------------------------------------------------------
__global__ void k_zero() {
    int i = blockIdx.x * blockDim.x + threadIdx.x;
    if (i < CH * CH)  g_G[i] = 0.0f;
    if (i < NC * CH)  g_sums[i] = 0.0f;
    if (i < NC)       g_counts[i] = 0.0f;
}

// ---------------------------------------------------------------
// K1: per-row inverse norms (one warp per row)
// ---------------------------------------------------------------
__global__ void k_norms(const float* __restrict__ x) {
    int warp = (blockIdx.x * blockDim.x + threadIdx.x) >> 5;
    int lane = threadIdx.x & 31;
    if (warp >= N_ROWS) return;
    const float* p = x + (size_t)warp * CH;
    float ss = 0.0f;
#pragma unroll
    for (int k = lane; k < CH; k += 32) {
        float v = p[k];
        ss += v * v;
    }
#pragma unroll
    for (int off = 16; off; off >>= 1)
        ss += __shfl_xor_sync(0xffffffffu, ss, off);
    if (lane == 0) g_invn[warp] = rsqrtf(ss);
}

// ---------------------------------------------------------------
// K2: per-row argmax of logits (== argmax of softmax), + class counts
// ---------------------------------------------------------------
__global__ void k_argmax(const float* __restrict__ lg) {
    int row = blockIdx.x;
    const float* p = lg + (size_t)row * NC;
    int tid = threadIdx.x;

    float best = -3.4e38f;
    int   bi = 0;
    for (int c = tid; c < NC; c += 128) {
        float v = p[c];
        if (v > best) { best = v; bi = c; }   // strided ascending -> '>' keeps first max
    }

    __shared__ float sv[128];
    __shared__ int   si[128];
    sv[tid] = best; si[tid] = bi;
    __syncthreads();
#pragma unroll
    for (int s = 64; s; s >>= 1) {
        if (tid < s) {
            float ov = sv[tid + s]; int oi = si[tid + s];
            if (ov > sv[tid] || (ov == sv[tid] && oi < si[tid])) {
                sv[tid] = ov; si[tid] = oi;
            }
        }
        __syncthreads();
    }
    if (tid == 0) {
        g_cls[row] = si[0];
        atomicAdd(&g_counts[si[0]], 1.0f);
    }
}

// ---------------------------------------------------------------
// K3: G = X^T D^{-1} X   (256x256, K=4096, K-split=16 with atomic reduce)
// grid (4,4,16), block (16,16); 64x64 tile, 4x4 micro-tile per thread
// ---------------------------------------------------------------
__global__ void k_gram(const float* __restrict__ x) {
    __shared__ float As[16][64];  // Xn[k][i-tile]
    __shared__ float Bs[16][64];  // X [k][j-tile]
    int i0 = blockIdx.x * 64, j0 = blockIdx.y * 64, k0 = blockIdx.z * 256;
    int tx = threadIdx.x, ty = threadIdx.y;
    int tid = ty * 16 + tx;

    float acc[4][4] = {};
    for (int kc = 0; kc < 256; kc += 16) {
#pragma unroll
        for (int l = 0; l < 4; l++) {
            int idx = tid + l * 256;        // 0..1023
            int kl = idx >> 6, col = idx & 63;
            int k = k0 + kc + kl;
            float inv = g_invn[k];
            As[kl][col] = x[(size_t)k * CH + i0 + col] * inv;
            Bs[kl][col] = x[(size_t)k * CH + j0 + col];
        }
        __syncthreads();
#pragma unroll
        for (int kl = 0; kl < 16; kl++) {
            float a[4], b[4];
#pragma unroll
            for (int u = 0; u < 4; u++) a[u] = As[kl][ty * 4 + u];
#pragma unroll
            for (int v = 0; v < 4; v++) b[v] = Bs[kl][tx * 4 + v];
#pragma unroll
            for (int u = 0; u < 4; u++)
#pragma unroll
                for (int v = 0; v < 4; v++)
                    acc[u][v] += a[u] * b[v];
        }
        __syncthreads();
    }
#pragma unroll
    for (int u = 0; u < 4; u++)
#pragma unroll
        for (int v = 0; v < 4; v++)
            atomicAdd(&g_G[(i0 + ty * 4 + u) * CH + j0 + tx * 4 + v], acc[u][v]);
}

// ---------------------------------------------------------------
// K4: P = X @ G ; y = invn[row]*P + x ; atomic scatter into class sums
// grid (64,4), block (16,16); 64(rows) x 64(cols) tile, k=256
// ---------------------------------------------------------------
__global__ void k_agg(const float* __restrict__ x) {
    __shared__ float As[64][17];  // x[row-tile][k-chunk], padded vs bank conflicts
    __shared__ float Bs[16][64];  // G[k][col-tile]
    int r0 = blockIdx.x * 64, c0 = blockIdx.y * 64;
    int tx = threadIdx.x, ty = threadIdx.y;
    int tid = ty * 16 + tx;

    float acc[4][4] = {};
    for (int k0 = 0; k0 < 256; k0 += 16) {
        // load A: 64 rows x 16 k's (coalesced in 64B segments per row)
#pragma unroll
        for (int l = 0; l < 4; l++) {
            int idx = tid + l * 256;         // 0..1023
            int r = idx >> 4, kl = idx & 15;
            As[r][kl] = x[(size_t)(r0 + r) * CH + k0 + kl];
        }
        // load B: 16 k's x 64 cols (fully coalesced)
#pragma unroll
        for (int l = 0; l < 4; l++) {
            int idx = tid + l * 256;
            int kl = idx >> 6, col = idx & 63;
            Bs[kl][col] = g_G[(k0 + kl) * CH + c0 + col];
        }
        __syncthreads();
#pragma unroll
        for (int kl = 0; kl < 16; kl++) {
            float a[4], b[4];
#pragma unroll
            for (int u = 0; u < 4; u++) a[u] = As[ty * 4 + u][kl];
#pragma unroll
            for (int v = 0; v < 4; v++) b[v] = Bs[kl][tx * 4 + v];
#pragma unroll
            for (int u = 0; u < 4; u++)
#pragma unroll
                for (int v = 0; v < 4; v++)
                    acc[u][v] += a[u] * b[v];
        }
        __syncthreads();
    }
    // epilogue: y = invn*acc + x, scatter-add to class sums
#pragma unroll
    for (int u = 0; u < 4; u++) {
        int row = r0 + ty * 4 + u;
        float inv = g_invn[row];
        int cls = g_cls[row];
#pragma unroll
        for (int v = 0; v < 4; v++) {
            int col = c0 + tx * 4 + v;
            float y = acc[u][v] * inv + x[(size_t)row * CH + col];
            atomicAdd(&g_sums[cls * CH + col], y);
        }
    }
}

// ---------------------------------------------------------------
// K5: prototypes = counts>0 ? sums/max(counts,1) : 0  -> d_out[0:NC*CH]
// ---------------------------------------------------------------
__global__ void k_proto(float* __restrict__ proto) {
    int c = blockIdx.x;
    int d = threadIdx.x;
    float cnt = g_counts[c];
    float v = 0.0f;
    if (cnt > 0.0f) v = g_sums[c * CH + d] / fmaxf(cnt, 1.0f);
    proto[c * CH + d] = v;
}

// ---------------------------------------------------------------
// K6: inter[i][j][:] = proto[j] - proto[i]   (1.02 GB, write-bound)
// 16x16 (i,j) tiles, proto rows cached in smem, float4 streaming stores
// ---------------------------------------------------------------
__global__ void k_inter(const float* __restrict__ proto, float* __restrict__ inter) {
    __shared__ float4 pi[16][64];
    __shared__ float4 pj[16][64];
    int i0 = blockIdx.y * 16, j0 = blockIdx.x * 16;
    int tid = threadIdx.x;               // 256 threads

    const float4* p4 = (const float4*)proto;
#pragma unroll
    for (int l = 0; l < 4; l++) {
        int idx = tid + l * 256;         // 0..1023
        int r = idx >> 6, d = idx & 63;
        int gi = i0 + r, gj = j0 + r;
        pi[r][d] = (gi < NC) ? p4[gi * 64 + d] : make_float4(0.f, 0.f, 0.f, 0.f);
        pj[r][d] = (gj < NC) ? p4[gj * 64 + d] : make_float4(0.f, 0.f, 0.f, 0.f);
    }
    __syncthreads();

    int d = tid & 63;
    int p0 = tid >> 6;                   // 0..3
    float4* o4 = (float4*)inter;
#pragma unroll 4
    for (int p = p0; p < 256; p += 4) {
        int il = p >> 4, jl = p & 15;
        int i = i0 + il, j = j0 + jl;
        if (i < NC && j < NC) {
            float4 a = pj[jl][d];
            float4 b = pi[il][d];
            float4 v = make_float4(a.x - b.x, a.y - b.y, a.z - b.z, a.w - b.w);
            __stcs(&o4[((size_t)i * NC + j) * 64 + d], v);
        }
    }
}

// ---------------------------------------------------------------
extern "C" void kernel_launch(void* const* d_in, const int* in_sizes, int n_in,
                              void* d_out, int out_size) {
    const float* x  = (const float*)d_in[0];   // [4096, 256]
    const float* lg = (const float*)d_in[1];   // [4096, 1000]
    float* out   = (float*)d_out;
    float* proto = out;                         // [1000, 256]
    float* inter = out + (size_t)NC * CH;       // [1000, 1000, 256]

    k_zero  <<<1000, 256>>>();
    k_norms <<<512, 256>>>(x);                  // 4096 warps
    k_argmax<<<N_ROWS, 128>>>(lg);
    k_gram  <<<dim3(4, 4, 16), dim3(16, 16)>>>(x);
    k_agg   <<<dim3(64, 4),   dim3(16, 16)>>>(x);
    k_proto <<<NC, CH>>>(proto);
    k_inter <<<dim3(63, 63), 256>>>(proto, inter);
}